// round 1
// baseline (speedup 1.0000x reference)
#include <cuda_runtime.h>
#include <cstdint>
#include <cstddef>

// ---------------- problem constants ----------------
#define Nn    32768
#define Dd    512
#define D2    1024
#define FIN   64
#define DOUT  128
#define EPS_MSG 1e-7f
#define EPS_LN  1e-5f

#define CHUNK_ROWS 512
#define NCHUNK (Nn / CHUNK_ROWS)   // 64

// ---------------- scratch (device globals; no allocation allowed) ----------------
__device__ float g_x[(size_t)Nn * Dd];     // 64 MB activation buffer
__device__ float g_z[(size_t)Nn * D2];     // 128 MB hidden buffer
__device__ float g_pmax[NCHUNK * Dd];
__device__ float g_pse [NCHUNK * Dd];
__device__ float g_psem[NCHUNK * Dd];
__device__ float g_cmax[Dd];
__device__ float g_agg [Dd];

// ---------------- SGEMM: C[M,N] = op(A)[M,K] @ B[K,N] (+bias, +Cin) ----------------
// AOP: 0 = identity, 1 = relu(a), 2 = relu(a) + agg[k]
// EPI: 0 = C = acc + bias[col]; 1 = C = Cin + acc + bias[col]
// Requires: M%128==0, N%128==0, K%16==0 (true for all 4 GEMMs here).
template<int AOP, int EPI>
__global__ void __launch_bounds__(256, 2)
sgemm_k(const float* __restrict__ A, const float* __restrict__ B,
        const float* __restrict__ bias, const float* __restrict__ agg,
        const float* __restrict__ Cin, float* __restrict__ C,
        int M, int N, int K)
{
    __shared__ float As[16][128];
    __shared__ float Bs[16][128];

    const int tid = threadIdx.x;
    const int tx  = tid & 15;          // 0..15 -> 8 cols each
    const int ty  = tid >> 4;          // 0..15 -> 8 rows each
    const size_t rowBase = (size_t)blockIdx.y * 128;
    const int    colBase = blockIdx.x * 128;

    const float* Ab = A + rowBase * (size_t)K;
    const float* Bb = B + colBase;

    float acc[8][8];
    #pragma unroll
    for (int i = 0; i < 8; ++i)
        #pragma unroll
        for (int j = 0; j < 8; ++j) acc[i][j] = 0.f;

    for (int k0 = 0; k0 < K; k0 += 16) {
        // load A tile [128 rows x 16 k] -> As[k][row] (transposed)
        #pragma unroll
        for (int i = 0; i < 2; ++i) {
            int e = tid + i * 256;         // 0..511 float4s
            int r = e >> 2;                // row 0..127
            int c = (e & 3) << 2;          // k offset 0,4,8,12
            float4 v = *(const float4*)(Ab + (size_t)r * K + (k0 + c));
            if (AOP >= 1) {
                v.x = fmaxf(v.x, 0.f); v.y = fmaxf(v.y, 0.f);
                v.z = fmaxf(v.z, 0.f); v.w = fmaxf(v.w, 0.f);
            }
            if (AOP == 2) {
                float4 ag = *(const float4*)(agg + k0 + c);
                v.x += ag.x; v.y += ag.y; v.z += ag.z; v.w += ag.w;
            }
            As[c + 0][r] = v.x; As[c + 1][r] = v.y;
            As[c + 2][r] = v.z; As[c + 3][r] = v.w;
        }
        // load B tile [16 k x 128 cols]
        #pragma unroll
        for (int i = 0; i < 2; ++i) {
            int e = tid + i * 256;
            int r = e >> 5;                // k 0..15
            int c = (e & 31) << 2;         // col 0..124
            *(float4*)&Bs[r][c] = *(const float4*)(Bb + (size_t)(k0 + r) * N + c);
        }
        __syncthreads();

        #pragma unroll
        for (int k = 0; k < 16; ++k) {
            float a[8], b[8];
            *(float4*)(&a[0]) = *(const float4*)(&As[k][ty * 8]);
            *(float4*)(&a[4]) = *(const float4*)(&As[k][ty * 8 + 4]);
            *(float4*)(&b[0]) = *(const float4*)(&Bs[k][tx * 8]);
            *(float4*)(&b[4]) = *(const float4*)(&Bs[k][tx * 8 + 4]);
            #pragma unroll
            for (int i = 0; i < 8; ++i)
                #pragma unroll
                for (int j = 0; j < 8; ++j)
                    acc[i][j] = fmaf(a[i], b[j], acc[i][j]);
        }
        __syncthreads();
    }

    // epilogue
    const int col = colBase + tx * 8;
    float4 bsv0 = *(const float4*)(bias + col);
    float4 bsv1 = *(const float4*)(bias + col + 4);
    #pragma unroll
    for (int i = 0; i < 8; ++i) {
        size_t r = rowBase + ty * 8 + i;
        float* Cp = C + r * (size_t)N + col;
        float4 o0, o1;
        o0.x = acc[i][0] + bsv0.x; o0.y = acc[i][1] + bsv0.y;
        o0.z = acc[i][2] + bsv0.z; o0.w = acc[i][3] + bsv0.w;
        o1.x = acc[i][4] + bsv1.x; o1.y = acc[i][5] + bsv1.y;
        o1.z = acc[i][6] + bsv1.z; o1.w = acc[i][7] + bsv1.w;
        if (EPI == 1) {
            const float4 c0 = *(const float4*)(Cin + r * (size_t)N + col);
            const float4 c1 = *(const float4*)(Cin + r * (size_t)N + col + 4);
            o0.x += c0.x; o0.y += c0.y; o0.z += c0.z; o0.w += c0.w;
            o1.x += c1.x; o1.y += c1.y; o1.z += c1.z; o1.w += c1.w;
        }
        *(float4*)(Cp)     = o0;
        *(float4*)(Cp + 4) = o1;
    }
}

// ---------------- per-channel softmax-aggregation reductions ----------------
// m = relu(x) + EPS_MSG ; v = t*m. Pass A: partial col-max of v.
__global__ void colmax_part_k(const float* __restrict__ x,
                              const float* __restrict__ tptr,
                              float* __restrict__ pmax)
{
    const float t = *tptr;
    const int cl   = threadIdx.x & 63;
    const int lane = threadIdx.x >> 6;          // 0..3
    const int c    = blockIdx.x * 64 + cl;
    const int r0   = blockIdx.y * CHUNK_ROWS;
    float mx = -1e30f;
    for (int r = r0 + lane; r < r0 + CHUNK_ROWS; r += 4) {
        float v = x[(size_t)r * Dd + c];
        v = t * (fmaxf(v, 0.f) + EPS_MSG);
        mx = fmaxf(mx, v);
    }
    __shared__ float s[256];
    s[threadIdx.x] = mx;
    __syncthreads();
    if (threadIdx.x < 64) {
        float m = fmaxf(fmaxf(s[cl], s[cl + 64]), fmaxf(s[cl + 128], s[cl + 192]));
        pmax[blockIdx.y * Dd + c] = m;
    }
}

__global__ void reduce_max_k(const float* __restrict__ pmax, float* __restrict__ cmax)
{
    int c = blockIdx.x * blockDim.x + threadIdx.x;
    if (c >= Dd) return;
    float m = -1e30f;
    #pragma unroll 4
    for (int ch = 0; ch < NCHUNK; ++ch) m = fmaxf(m, pmax[ch * Dd + c]);
    cmax[c] = m;
}

// Pass B: partial sum of e=exp(t*m - cmax) and e*m.
__global__ void colsum_part_k(const float* __restrict__ x,
                              const float* __restrict__ tptr,
                              const float* __restrict__ cmax,
                              float* __restrict__ pse, float* __restrict__ psem)
{
    const float t = *tptr;
    const int cl   = threadIdx.x & 63;
    const int lane = threadIdx.x >> 6;
    const int c    = blockIdx.x * 64 + cl;
    const int r0   = blockIdx.y * CHUNK_ROWS;
    const float cm = cmax[c];
    float se = 0.f, sem = 0.f;
    for (int r = r0 + lane; r < r0 + CHUNK_ROWS; r += 4) {
        float v = x[(size_t)r * Dd + c];
        float m = fmaxf(v, 0.f) + EPS_MSG;
        float e = __expf(fmaf(t, m, -cm));
        se  += e;
        sem = fmaf(e, m, sem);
    }
    __shared__ float s1[256];
    __shared__ float s2[256];
    s1[threadIdx.x] = se; s2[threadIdx.x] = sem;
    __syncthreads();
    if (threadIdx.x < 64) {
        float a = s1[cl] + s1[cl + 64] + s1[cl + 128] + s1[cl + 192];
        float b = s2[cl] + s2[cl + 64] + s2[cl + 128] + s2[cl + 192];
        pse [blockIdx.y * Dd + c] = a;
        psem[blockIdx.y * Dd + c] = b;
    }
}

__global__ void reduce_agg_k(const float* __restrict__ pse,
                             const float* __restrict__ psem,
                             float* __restrict__ agg)
{
    int c = blockIdx.x * blockDim.x + threadIdx.x;
    if (c >= Dd) return;
    float se = 0.f, sem = 0.f;
    #pragma unroll 4
    for (int ch = 0; ch < NCHUNK; ++ch) { se += pse[ch * Dd + c]; sem += psem[ch * Dd + c]; }
    agg[c] = sem / se;
}

// ---------------- fused LayerNorm + ReLU over rows of length 1024 ----------------
__global__ void ln_relu_k(float* __restrict__ z,
                          const float* __restrict__ gam,
                          const float* __restrict__ bet)
{
    __shared__ float2 sred[8];
    const size_t row = blockIdx.x;
    float4* zr = (float4*)(z + row * (size_t)D2);
    float4 v = zr[threadIdx.x];                    // 256 threads x 4 = 1024
    float s  = v.x + v.y + v.z + v.w;
    float ss = fmaf(v.x, v.x, fmaf(v.y, v.y, fmaf(v.z, v.z, v.w * v.w)));
    #pragma unroll
    for (int o = 16; o; o >>= 1) {
        s  += __shfl_xor_sync(0xffffffffu, s,  o);
        ss += __shfl_xor_sync(0xffffffffu, ss, o);
    }
    if ((threadIdx.x & 31) == 0) sred[threadIdx.x >> 5] = make_float2(s, ss);
    __syncthreads();
    float S = 0.f, SS = 0.f;
    #pragma unroll
    for (int i = 0; i < 8; ++i) { S += sred[i].x; SS += sred[i].y; }
    const float mu  = S * (1.f / 1024.f);
    const float var = SS * (1.f / 1024.f) - mu * mu;
    const float inv = rsqrtf(var + EPS_LN);
    const int c = threadIdx.x * 4;
    const float4 gg = *(const float4*)(gam + c);
    const float4 bb = *(const float4*)(bet + c);
    v.x = fmaxf(fmaf((v.x - mu) * inv, gg.x, bb.x), 0.f);
    v.y = fmaxf(fmaf((v.y - mu) * inv, gg.y, bb.y), 0.f);
    v.z = fmaxf(fmaf((v.z - mu) * inv, gg.z, bb.z), 0.f);
    v.w = fmaxf(fmaf((v.w - mu) * inv, gg.w, bb.w), 0.f);
    zr[threadIdx.x] = v;
}

// ---------------- host launcher ----------------
extern "C" void kernel_launch(void* const* d_in, const int* in_sizes, int n_in,
                              void* d_out, int out_size)
{
    const float* batch = (const float*)d_in[0];
    const float* W_enc = (const float*)d_in[1];
    const float* b_enc = (const float*)d_in[2];
    const float* Wf    = (const float*)d_in[3];
    const float* bf    = (const float*)d_in[4];
    const float* t [2] = {(const float*)d_in[5],  (const float*)d_in[12]};
    const float* W1[2] = {(const float*)d_in[6],  (const float*)d_in[13]};
    const float* b1[2] = {(const float*)d_in[7],  (const float*)d_in[14]};
    const float* g [2] = {(const float*)d_in[8],  (const float*)d_in[15]};
    const float* be[2] = {(const float*)d_in[9],  (const float*)d_in[16]};
    const float* W2[2] = {(const float*)d_in[10], (const float*)d_in[17]};
    const float* b2[2] = {(const float*)d_in[11], (const float*)d_in[18]};

    float *x, *z, *pmax, *pse, *psem, *cmax, *agg;
    cudaGetSymbolAddress((void**)&x,    g_x);
    cudaGetSymbolAddress((void**)&z,    g_z);
    cudaGetSymbolAddress((void**)&pmax, g_pmax);
    cudaGetSymbolAddress((void**)&pse,  g_pse);
    cudaGetSymbolAddress((void**)&psem, g_psem);
    cudaGetSymbolAddress((void**)&cmax, g_cmax);
    cudaGetSymbolAddress((void**)&agg,  g_agg);

    const dim3 gEnc(Dd / 128,  Nn / 128);   // (4, 256)
    const dim3 gG1 (D2 / 128,  Nn / 128);   // (8, 256)
    const dim3 gG2 (Dd / 128,  Nn / 128);   // (4, 256)
    const dim3 gFin(DOUT / 128, Nn / 128);  // (1, 256)
    const dim3 gCol(Dd / 64, NCHUNK);       // (8, 64)

    // encoder: x = batch @ W_enc + b_enc
    sgemm_k<0, 0><<<gEnc, 256>>>(batch, W_enc, b_enc, nullptr, nullptr, x, Nn, Dd, FIN);

    for (int l = 0; l < 2; ++l) {
        colmax_part_k<<<gCol, 256>>>(x, t[l], pmax);
        reduce_max_k <<<2, 256>>>(pmax, cmax);
        colsum_part_k<<<gCol, 256>>>(x, t[l], cmax, pse, psem);
        reduce_agg_k <<<2, 256>>>(pse, psem, agg);
        // z = (relu(x) + agg) @ W1 + b1
        sgemm_k<2, 0><<<gG1, 256>>>(x, W1[l], b1[l], agg, nullptr, z, Nn, D2, Dd);
        // z = relu(LN(z))
        ln_relu_k<<<Nn, 256>>>(z, g[l], be[l]);
        // x = x + z @ W2 + b2
        sgemm_k<0, 1><<<gG2, 256>>>(z, W2[l], b2[l], nullptr, x, x, Nn, Dd, D2);
    }

    // out = relu(x) @ Wf + bf
    sgemm_k<1, 0><<<gFin, 256>>>(x, Wf, bf, nullptr, nullptr, (float*)d_out, Nn, DOUT, Dd);
}

// round 3
// speedup vs baseline: 2.2240x; 2.2240x over previous
#include <cuda_runtime.h>
#include <cuda_bf16.h>
#include <cstdint>
#include <cstddef>

// ---------------- problem constants ----------------
#define Nn    32768
#define Dd    512
#define D2    1024
#define FIN   64
#define DOUT  128
#define EPS_MSG 1e-7f
#define EPS_LN  1e-5f

#define CHUNK_ROWS 512
#define NCHUNK (Nn / CHUNK_ROWS)   // 64

// ---------------- scratch (device globals; no allocation allowed) ----------------
__device__ float g_x[(size_t)Nn * Dd];          // fp32 activations (residual stream)
__device__ float g_z[(size_t)Nn * D2];          // fp32 hidden (GEMM1 out, LN in)
__device__ __nv_bfloat16 g_ah[(size_t)Nn * D2]; // A operand hi
__device__ __nv_bfloat16 g_al[(size_t)Nn * D2]; // A operand lo
// transposed+split weights [N,K] bf16, packed at fixed offsets
#define OFF_ENC   0
#define OFF_W1_0  32768
#define OFF_W2_0  557056
#define OFF_W1_1  1081344
#define OFF_W2_1  1605632
#define OFF_WF    2129920
#define WTOT      2195456
__device__ __nv_bfloat16 g_wh[WTOT];
__device__ __nv_bfloat16 g_wl[WTOT];
__device__ float g_pmax[NCHUNK * Dd];
__device__ float g_pse [NCHUNK * Dd];
__device__ float g_psem[NCHUNK * Dd];
__device__ float g_cmax[Dd];
__device__ float g_agg [Dd];

// ---------------- PTX helpers (sm_80-level; compile for plain sm_103) ----------------
__device__ __forceinline__ uint32_t smem_u32(const void* p) {
    uint32_t a;
    asm("{ .reg .u64 t; cvta.to.shared.u64 t, %1; cvt.u32.u64 %0, t; }" : "=r"(a) : "l"(p));
    return a;
}

__device__ __forceinline__ void cpa16(uint32_t saddr, const void* gaddr) {
    asm volatile("cp.async.cg.shared.global [%0], [%1], 16;"
                 :: "r"(saddr), "l"(__cvta_generic_to_global(gaddr)));
}
#define CP_COMMIT() asm volatile("cp.async.commit_group;" ::: "memory")
#define CP_WAIT1()  asm volatile("cp.async.wait_group 1;" ::: "memory")
#define CP_WAIT0()  asm volatile("cp.async.wait_group 0;" ::: "memory")

__device__ __forceinline__ void ldsm4(uint32_t& r0, uint32_t& r1, uint32_t& r2, uint32_t& r3,
                                      uint32_t addr) {
    asm volatile("ldmatrix.sync.aligned.m8n8.x4.shared.b16 {%0,%1,%2,%3}, [%4];"
                 : "=r"(r0), "=r"(r1), "=r"(r2), "=r"(r3) : "r"(addr));
}

__device__ __forceinline__ void mma16816(float* d, const uint32_t* a, const uint32_t* b) {
    asm volatile("mma.sync.aligned.m16n8k16.row.col.f32.bf16.bf16.f32 "
                 "{%0,%1,%2,%3}, {%4,%5,%6,%7}, {%8,%9}, {%0,%1,%2,%3};"
                 : "+f"(d[0]), "+f"(d[1]), "+f"(d[2]), "+f"(d[3])
                 : "r"(a[0]), "r"(a[1]), "r"(a[2]), "r"(a[3]), "r"(b[0]), "r"(b[1]));
}

#define SWZ(o) ((o) ^ (((o) >> 3) & 0x70))

// ---------------- stage loader: 4 arrays x 128 rows x 64 bf16 (SW128 swizzled) ----------------
__device__ __forceinline__ void load_stage(uint32_t sbase, int s,
                                           const __nv_bfloat16* a0, const __nv_bfloat16* a1,
                                           const __nv_bfloat16* b0, const __nv_bfloat16* b1,
                                           int K, int k0, int tid)
{
    const uint32_t base = sbase + (uint32_t)s * 65536u;
    const __nv_bfloat16* srcs[4] = {a0 + k0, a1 + k0, b0 + k0, b1 + k0};
    #pragma unroll
    for (int arr = 0; arr < 4; ++arr) {
        const uint32_t ab = base + (uint32_t)arr * 16384u;
        const __nv_bfloat16* src = srcs[arr];
        #pragma unroll
        for (int i = 0; i < 4; ++i) {
            int id = tid + i * 256;
            int r = id >> 3, j = id & 7;
            uint32_t off = (uint32_t)(r * 128 + j * 16);
            cpa16(ab + SWZ(off), src + (size_t)r * K + j * 8);
        }
    }
}

// ---------------- split-bf16 tensor-core GEMM via mma.sync ----------------
// C[M,N] = (Ahi+Alo)[M,K] @ (Bhi+Blo)^T, B stored [N,K] K-major. (+bias, +Cin)
// CTA 128x128x64, 256 thr, 8 warps (2x4), warp tile 64x32. 2-stage cp.async pipeline.
template<int EPI>
__global__ void __launch_bounds__(256, 1)
hgemm_k(const __nv_bfloat16* __restrict__ Ahi, const __nv_bfloat16* __restrict__ Alo,
        const __nv_bfloat16* __restrict__ Bhi, const __nv_bfloat16* __restrict__ Blo,
        const float* __restrict__ bias, const float* __restrict__ Cin,
        float* __restrict__ C, int K, int N)
{
    extern __shared__ char sm[];
    const uint32_t sb = smem_u32(sm);
    const int tid = threadIdx.x;
    const int lane = tid & 31;
    const int wid = tid >> 5;
    const int wm = (wid >> 2) * 64;     // warp m offset in block
    const int wn = (wid & 3) * 32;      // warp n offset in block
    const size_t rowBase = (size_t)blockIdx.y * 128;
    const int    colBase = blockIdx.x * 128;
    const int KC = K >> 6;

    const __nv_bfloat16* gAh = Ahi + rowBase * (size_t)K;
    const __nv_bfloat16* gAl = Alo + rowBase * (size_t)K;
    const __nv_bfloat16* gBh = Bhi + (size_t)colBase * K;
    const __nv_bfloat16* gBl = Blo + (size_t)colBase * K;

    float acc[4][4][4];
    #pragma unroll
    for (int i = 0; i < 4; ++i)
        #pragma unroll
        for (int j = 0; j < 4; ++j)
            #pragma unroll
            for (int q = 0; q < 4; ++q) acc[i][j][q] = 0.f;

    load_stage(sb, 0, gAh, gAl, gBh, gBl, K, 0, tid);
    CP_COMMIT();

    const int lr = lane & 15;           // row within 16-row ldmatrix group
    const int lc = lane >> 4;           // k-half selector

    for (int c = 0; c < KC; ++c) {
        if (c + 1 < KC) {
            load_stage(sb, (c + 1) & 1, gAh, gAl, gBh, gBl, K, (c + 1) * 64, tid);
            CP_COMMIT();
            CP_WAIT1();
        } else {
            CP_WAIT0();
        }
        __syncthreads();

        const uint32_t aAh = sb + (uint32_t)(c & 1) * 65536u;
        const uint32_t aAl = aAh + 16384u;
        const uint32_t aBh = aAh + 32768u;
        const uint32_t aBl = aAh + 49152u;

        #pragma unroll
        for (int kk = 0; kk < 4; ++kk) {
            uint32_t ah[4][4], al[4][4], bh[4][2], bl[4][2];
            #pragma unroll
            for (int mt = 0; mt < 4; ++mt) {
                uint32_t off = (uint32_t)((wm + mt * 16 + lr) * 128 + kk * 32 + lc * 16);
                uint32_t so = SWZ(off);
                ldsm4(ah[mt][0], ah[mt][1], ah[mt][2], ah[mt][3], aAh + so);
                ldsm4(al[mt][0], al[mt][1], al[mt][2], al[mt][3], aAl + so);
            }
            #pragma unroll
            for (int np = 0; np < 2; ++np) {
                uint32_t off = (uint32_t)((wn + np * 16 + lr) * 128 + kk * 32 + lc * 16);
                uint32_t so = SWZ(off);
                uint32_t r0, r1, r2, r3;
                ldsm4(r0, r1, r2, r3, aBh + so);
                bh[np * 2][0] = r0; bh[np * 2 + 1][0] = r1;
                bh[np * 2][1] = r2; bh[np * 2 + 1][1] = r3;
                ldsm4(r0, r1, r2, r3, aBl + so);
                bl[np * 2][0] = r0; bl[np * 2 + 1][0] = r1;
                bl[np * 2][1] = r2; bl[np * 2 + 1][1] = r3;
            }
            #pragma unroll
            for (int mt = 0; mt < 4; ++mt)
                #pragma unroll
                for (int nt = 0; nt < 4; ++nt) {
                    mma16816(acc[mt][nt], ah[mt], bh[nt]);
                    mma16816(acc[mt][nt], ah[mt], bl[nt]);
                    mma16816(acc[mt][nt], al[mt], bh[nt]);
                }
        }
        __syncthreads();
    }

    // ---------------- epilogue ----------------
    const int l4 = lane >> 2;
    const int l2 = (lane & 3) * 2;
    float2 bv[4];
    #pragma unroll
    for (int nt = 0; nt < 4; ++nt)
        bv[nt] = *(const float2*)(bias + colBase + wn + nt * 8 + l2);

    #pragma unroll
    for (int mt = 0; mt < 4; ++mt) {
        const size_t m0 = rowBase + wm + mt * 16 + l4;
        #pragma unroll
        for (int nt = 0; nt < 4; ++nt) {
            const int n = colBase + wn + nt * 8 + l2;
            float2 o0, o1;
            o0.x = acc[mt][nt][0] + bv[nt].x;
            o0.y = acc[mt][nt][1] + bv[nt].y;
            o1.x = acc[mt][nt][2] + bv[nt].x;
            o1.y = acc[mt][nt][3] + bv[nt].y;
            if (EPI) {
                float2 c0 = *(const float2*)(Cin + m0 * (size_t)N + n);
                float2 c1 = *(const float2*)(Cin + (m0 + 8) * (size_t)N + n);
                o0.x += c0.x; o0.y += c0.y;
                o1.x += c1.x; o1.y += c1.y;
            }
            *(float2*)(C + m0 * (size_t)N + n)       = o0;
            *(float2*)(C + (m0 + 8) * (size_t)N + n) = o1;
        }
    }
}

// ---------------- fp32 -> bf16 hi/lo split helpers ----------------
__device__ __forceinline__ void split4(const float* a, unsigned short* hb, unsigned short* lb) {
    #pragma unroll
    for (int j = 0; j < 4; ++j) {
        __nv_bfloat16 h = __float2bfloat16_rn(a[j]);
        float r = a[j] - __bfloat162float(h);
        __nv_bfloat16 l = __float2bfloat16_rn(r);
        hb[j] = __bfloat16_as_ushort(h);
        lb[j] = __bfloat16_as_ushort(l);
    }
}

// AOP: 0 = identity, 1 = relu, 2 = relu + agg[col]
template<int AOP>
__global__ void conv_k(const float* __restrict__ src, const float* __restrict__ agg,
                       __nv_bfloat16* __restrict__ hi, __nv_bfloat16* __restrict__ lo,
                       int total4, int kmask)
{
    int i = blockIdx.x * blockDim.x + threadIdx.x;
    if (i >= total4) return;
    float4 v = ((const float4*)src)[i];
    float a[4] = {v.x, v.y, v.z, v.w};
    if (AOP >= 1) {
        #pragma unroll
        for (int j = 0; j < 4; ++j) a[j] = fmaxf(a[j], 0.f);
    }
    if (AOP == 2) {
        float4 ag = *(const float4*)(agg + ((i * 4) & kmask));
        a[0] += ag.x; a[1] += ag.y; a[2] += ag.z; a[3] += ag.w;
    }
    unsigned short hb[4], lb[4];
    split4(a, hb, lb);
    uint2 uh, ul;
    uh.x = (uint32_t)hb[0] | ((uint32_t)hb[1] << 16);
    uh.y = (uint32_t)hb[2] | ((uint32_t)hb[3] << 16);
    ul.x = (uint32_t)lb[0] | ((uint32_t)lb[1] << 16);
    ul.y = (uint32_t)lb[2] | ((uint32_t)lb[3] << 16);
    *(uint2*)(hi + (size_t)i * 4) = uh;
    *(uint2*)(lo + (size_t)i * 4) = ul;
}

// ---------------- weight transpose + split: W[K,N] -> Thi/Tlo[N,K] ----------------
__global__ void wtrans_k(const float* __restrict__ W,
                         __nv_bfloat16* __restrict__ Thi, __nv_bfloat16* __restrict__ Tlo,
                         int K, int N)
{
    __shared__ float tile[32][33];
    int k0 = blockIdx.y * 32, n0 = blockIdx.x * 32;
    int tx = threadIdx.x, ty = threadIdx.y;
    #pragma unroll
    for (int i = ty; i < 32; i += 8)
        tile[i][tx] = W[(size_t)(k0 + i) * N + n0 + tx];
    __syncthreads();
    #pragma unroll
    for (int i = ty; i < 32; i += 8) {
        float v = tile[tx][i];                       // = W[k0+tx][n0+i]
        __nv_bfloat16 h = __float2bfloat16_rn(v);
        float r = v - __bfloat162float(h);
        size_t o = (size_t)(n0 + i) * K + k0 + tx;
        Thi[o] = h;
        Tlo[o] = __float2bfloat16_rn(r);
    }
}

// ---------------- per-channel softmax-aggregation reductions ----------------
__global__ void colmax_part_k(const float* __restrict__ x,
                              const float* __restrict__ tptr,
                              float* __restrict__ pmax)
{
    const float t = *tptr;
    const int cl = threadIdx.x & 63;
    const int lane = threadIdx.x >> 6;
    const int c = blockIdx.x * 64 + cl;
    const int r0 = blockIdx.y * CHUNK_ROWS;
    float mx = -1e30f;
    for (int r = r0 + lane; r < r0 + CHUNK_ROWS; r += 4) {
        float v = x[(size_t)r * Dd + c];
        v = t * (fmaxf(v, 0.f) + EPS_MSG);
        mx = fmaxf(mx, v);
    }
    __shared__ float s[256];
    s[threadIdx.x] = mx;
    __syncthreads();
    if (threadIdx.x < 64) {
        float m = fmaxf(fmaxf(s[cl], s[cl + 64]), fmaxf(s[cl + 128], s[cl + 192]));
        pmax[blockIdx.y * Dd + c] = m;
    }
}

__global__ void reduce_max_k(const float* __restrict__ pmax, float* __restrict__ cmax)
{
    int c = blockIdx.x * blockDim.x + threadIdx.x;
    if (c >= Dd) return;
    float m = -1e30f;
    #pragma unroll 4
    for (int ch = 0; ch < NCHUNK; ++ch) m = fmaxf(m, pmax[ch * Dd + c]);
    cmax[c] = m;
}

__global__ void colsum_part_k(const float* __restrict__ x,
                              const float* __restrict__ tptr,
                              const float* __restrict__ cmax,
                              float* __restrict__ pse, float* __restrict__ psem)
{
    const float t = *tptr;
    const int cl = threadIdx.x & 63;
    const int lane = threadIdx.x >> 6;
    const int c = blockIdx.x * 64 + cl;
    const int r0 = blockIdx.y * CHUNK_ROWS;
    const float cm = cmax[c];
    float se = 0.f, sem = 0.f;
    for (int r = r0 + lane; r < r0 + CHUNK_ROWS; r += 4) {
        float v = x[(size_t)r * Dd + c];
        float m = fmaxf(v, 0.f) + EPS_MSG;
        float e = __expf(fmaf(t, m, -cm));
        se += e;
        sem = fmaf(e, m, sem);
    }
    __shared__ float s1[256];
    __shared__ float s2[256];
    s1[threadIdx.x] = se; s2[threadIdx.x] = sem;
    __syncthreads();
    if (threadIdx.x < 64) {
        float a = s1[cl] + s1[cl + 64] + s1[cl + 128] + s1[cl + 192];
        float b = s2[cl] + s2[cl + 64] + s2[cl + 128] + s2[cl + 192];
        pse [blockIdx.y * Dd + c] = a;
        psem[blockIdx.y * Dd + c] = b;
    }
}

__global__ void reduce_agg_k(const float* __restrict__ pse,
                             const float* __restrict__ psem,
                             float* __restrict__ agg)
{
    int c = blockIdx.x * blockDim.x + threadIdx.x;
    if (c >= Dd) return;
    float se = 0.f, sem = 0.f;
    #pragma unroll 4
    for (int ch = 0; ch < NCHUNK; ++ch) { se += pse[ch * Dd + c]; sem += psem[ch * Dd + c]; }
    agg[c] = sem / se;
}

// ---------------- fused LayerNorm + ReLU + bf16 split (row length 1024) ----------------
__global__ void ln_relu_k(const float* __restrict__ z,
                          const float* __restrict__ gam, const float* __restrict__ bet,
                          __nv_bfloat16* __restrict__ zhi, __nv_bfloat16* __restrict__ zlo)
{
    __shared__ float2 sred[8];
    const size_t row = blockIdx.x;
    const float4* zr = (const float4*)(z + row * (size_t)D2);
    float4 v = zr[threadIdx.x];
    float s  = v.x + v.y + v.z + v.w;
    float ss = fmaf(v.x, v.x, fmaf(v.y, v.y, fmaf(v.z, v.z, v.w * v.w)));
    #pragma unroll
    for (int o = 16; o; o >>= 1) {
        s  += __shfl_xor_sync(0xffffffffu, s,  o);
        ss += __shfl_xor_sync(0xffffffffu, ss, o);
    }
    if ((threadIdx.x & 31) == 0) sred[threadIdx.x >> 5] = make_float2(s, ss);
    __syncthreads();
    float S = 0.f, SS = 0.f;
    #pragma unroll
    for (int i = 0; i < 8; ++i) { S += sred[i].x; SS += sred[i].y; }
    const float mu  = S * (1.f / 1024.f);
    const float var = SS * (1.f / 1024.f) - mu * mu;
    const float inv = rsqrtf(var + EPS_LN);
    const int c = threadIdx.x * 4;
    const float4 gg = *(const float4*)(gam + c);
    const float4 bb = *(const float4*)(bet + c);
    float a[4];
    a[0] = fmaxf(fmaf((v.x - mu) * inv, gg.x, bb.x), 0.f);
    a[1] = fmaxf(fmaf((v.y - mu) * inv, gg.y, bb.y), 0.f);
    a[2] = fmaxf(fmaf((v.z - mu) * inv, gg.z, bb.z), 0.f);
    a[3] = fmaxf(fmaf((v.w - mu) * inv, gg.w, bb.w), 0.f);
    unsigned short hb[4], lb[4];
    split4(a, hb, lb);
    uint2 uh, ul;
    uh.x = (uint32_t)hb[0] | ((uint32_t)hb[1] << 16);
    uh.y = (uint32_t)hb[2] | ((uint32_t)hb[3] << 16);
    ul.x = (uint32_t)lb[0] | ((uint32_t)lb[1] << 16);
    ul.y = (uint32_t)lb[2] | ((uint32_t)lb[3] << 16);
    *(uint2*)(zhi + row * (size_t)D2 + c) = uh;
    *(uint2*)(zlo + row * (size_t)D2 + c) = ul;
}

// ---------------- host launcher ----------------
extern "C" void kernel_launch(void* const* d_in, const int* in_sizes, int n_in,
                              void* d_out, int out_size)
{
    const float* batch = (const float*)d_in[0];
    const float* W_enc = (const float*)d_in[1];
    const float* b_enc = (const float*)d_in[2];
    const float* Wf    = (const float*)d_in[3];
    const float* bf    = (const float*)d_in[4];
    const float* t [2] = {(const float*)d_in[5],  (const float*)d_in[12]};
    const float* W1[2] = {(const float*)d_in[6],  (const float*)d_in[13]};
    const float* b1[2] = {(const float*)d_in[7],  (const float*)d_in[14]};
    const float* g [2] = {(const float*)d_in[8],  (const float*)d_in[15]};
    const float* be[2] = {(const float*)d_in[9],  (const float*)d_in[16]};
    const float* W2[2] = {(const float*)d_in[10], (const float*)d_in[17]};
    const float* b2[2] = {(const float*)d_in[11], (const float*)d_in[18]};

    float *x, *z, *pmax, *pse, *psem, *cmax, *agg;
    __nv_bfloat16 *ah, *al, *wh, *wl;
    cudaGetSymbolAddress((void**)&x,    g_x);
    cudaGetSymbolAddress((void**)&z,    g_z);
    cudaGetSymbolAddress((void**)&ah,   g_ah);
    cudaGetSymbolAddress((void**)&al,   g_al);
    cudaGetSymbolAddress((void**)&wh,   g_wh);
    cudaGetSymbolAddress((void**)&wl,   g_wl);
    cudaGetSymbolAddress((void**)&pmax, g_pmax);
    cudaGetSymbolAddress((void**)&pse,  g_pse);
    cudaGetSymbolAddress((void**)&psem, g_psem);
    cudaGetSymbolAddress((void**)&cmax, g_cmax);
    cudaGetSymbolAddress((void**)&agg,  g_agg);

    const int SMEM = 131072;   // 2 stages x 64KB
    cudaFuncSetAttribute(hgemm_k<0>, cudaFuncAttributeMaxDynamicSharedMemorySize, SMEM);
    cudaFuncSetAttribute(hgemm_k<1>, cudaFuncAttributeMaxDynamicSharedMemorySize, SMEM);

    // ---- weight transpose + split ----
    wtrans_k<<<dim3(Dd/32,  FIN/32), dim3(32,8)>>>(W_enc, wh + OFF_ENC,  wl + OFF_ENC,  FIN, Dd);
    wtrans_k<<<dim3(D2/32,  Dd/32),  dim3(32,8)>>>(W1[0], wh + OFF_W1_0, wl + OFF_W1_0, Dd,  D2);
    wtrans_k<<<dim3(Dd/32,  D2/32),  dim3(32,8)>>>(W2[0], wh + OFF_W2_0, wl + OFF_W2_0, D2,  Dd);
    wtrans_k<<<dim3(D2/32,  Dd/32),  dim3(32,8)>>>(W1[1], wh + OFF_W1_1, wl + OFF_W1_1, Dd,  D2);
    wtrans_k<<<dim3(Dd/32,  D2/32),  dim3(32,8)>>>(W2[1], wh + OFF_W2_1, wl + OFF_W2_1, D2,  Dd);
    wtrans_k<<<dim3(DOUT/32, Dd/32), dim3(32,8)>>>(Wf,    wh + OFF_WF,   wl + OFF_WF,   Dd,  DOUT);

    // ---- encoder: x = batch @ W_enc + b_enc ----
    conv_k<0><<<(Nn * FIN / 4 + 255) / 256, 256>>>(batch, nullptr, ah, al, Nn * FIN / 4, 0);
    hgemm_k<0><<<dim3(Dd/128, Nn/128), 256, SMEM>>>(
        ah, al, wh + OFF_ENC, wl + OFF_ENC, b_enc, nullptr, x, FIN, Dd);

    const size_t woff1[2] = {OFF_W1_0, OFF_W1_1};
    const size_t woff2[2] = {OFF_W2_0, OFF_W2_1};
    const dim3 gCol(Dd / 64, NCHUNK);

    for (int l = 0; l < 2; ++l) {
        colmax_part_k<<<gCol, 256>>>(x, t[l], pmax);
        reduce_max_k <<<2, 256>>>(pmax, cmax);
        colsum_part_k<<<gCol, 256>>>(x, t[l], cmax, pse, psem);
        reduce_agg_k <<<2, 256>>>(pse, psem, agg);
        // A = relu(x) + agg -> bf16 split
        conv_k<2><<<Nn * Dd / 4 / 256, 256>>>(x, agg, ah, al, Nn * Dd / 4, Dd - 1);
        // z = A @ W1 + b1
        hgemm_k<0><<<dim3(D2/128, Nn/128), 256, SMEM>>>(
            ah, al, wh + woff1[l], wl + woff1[l], b1[l], nullptr, z, Dd, D2);
        // A' = relu(LN(z)) -> bf16 split
        ln_relu_k<<<Nn, 256>>>(z, g[l], be[l], ah, al);
        // x = x + A' @ W2 + b2
        hgemm_k<1><<<dim3(Dd/128, Nn/128), 256, SMEM>>>(
            ah, al, wh + woff2[l], wl + woff2[l], b2[l], x, x, D2, Dd);
    }

    // ---- final: out = relu(x) @ Wf + bf ----
    conv_k<1><<<Nn * Dd / 4 / 256, 256>>>(x, nullptr, ah, al, Nn * Dd / 4, 0);
    hgemm_k<0><<<dim3(DOUT/128, Nn/128), 256, SMEM>>>(
        ah, al, wh + OFF_WF, wl + OFF_WF, bf, nullptr, (float*)d_out, Dd, DOUT);
}